// round 7
// baseline (speedup 1.0000x reference)
#include <cuda_runtime.h>
#include <cuda_fp16.h>

typedef unsigned int u32;

#define TT 1024
#define BB 512
#define FI 128
#define UU 256
#define PP 1024        // 4*U permuted: 16-block b16=P>>4; c<8 -> i,f ; c>=8 -> o,g
#define RC_CTAS 128
#define CLU 8          // cluster = one batch group (32 rows), 8 CTAs x 128 P-cols

// ---------------- device scratch ----------------
__device__ __half g_WT[PP * FI];          // W^T permuted [P][f]
__device__ __half g_RT[PP * UU];          // R^T permuted [P][k]
__device__ __half g_h[2][BB * UU];        // h state, double buffered
__device__ float g_bp[PP];
__device__ __half g_xk[(size_t)TT * BB * PP];   // fp16 scratch [(t*512+b)*1024+P]

// ---------------- helpers ----------------
__device__ __forceinline__ u32 s2u(const void* p) {
    u32 a;
    asm("{ .reg .u64 t; cvta.to.shared.u64 t, %1; cvt.u32.u64 %0, t; }" : "=r"(a) : "l"(p));
    return a;
}
__device__ __forceinline__ void ldsm4(u32 addr, u32* r) {
    asm volatile("ldmatrix.sync.aligned.m8n8.x4.shared.b16 {%0,%1,%2,%3}, [%4];"
                 : "=r"(r[0]), "=r"(r[1]), "=r"(r[2]), "=r"(r[3]) : "r"(addr));
}
__device__ __forceinline__ void mma16816(float* c, const u32* a, u32 b0, u32 b1) {
    asm volatile(
        "mma.sync.aligned.m16n8k16.row.col.f32.f16.f16.f32 "
        "{%0,%1,%2,%3},{%4,%5,%6,%7},{%8,%9},{%0,%1,%2,%3};"
        : "+f"(c[0]), "+f"(c[1]), "+f"(c[2]), "+f"(c[3])
        : "r"(a[0]), "r"(a[1]), "r"(a[2]), "r"(a[3]), "r"(b0), "r"(b1));
}
__device__ __forceinline__ float sig_fast(float x) {
    return __fdividef(1.0f, 1.0f + __expf(-x));
}
__device__ __forceinline__ float tanh_acc(float x) {
    return __fdividef(2.0f, 1.0f + __expf(-2.0f * x)) - 1.0f;
}
__device__ __forceinline__ int origcol(int P) {   // permuted col -> keras col
    int blk = P >> 4, c = P & 15;
    int u = 4 * blk + ((c >> 1) & 3);
    int g = ((c >> 3) << 1) | (c & 1);            // 0:i 1:f 2:o 3:g
    return g * UU + u;
}

// ================= prep =================
__global__ void lstm_prep(const float* __restrict__ W, const float* __restrict__ R,
                          const float* __restrict__ bias, const float* __restrict__ h0) {
    int i = blockIdx.x * blockDim.x + threadIdx.x;
    if (i < PP * FI) {
        int P = i >> 7, f = i & 127;
        g_WT[i] = __float2half_rn(W[f * PP + origcol(P)]);
    } else if (i < PP * FI + PP * UU) {
        int j = i - PP * FI;
        int P = j >> 8, k = j & 255;
        g_RT[j] = __float2half_rn(R[k * PP + origcol(P)]);
    } else if (i < PP * FI + PP * UU + PP) {
        int P = i - PP * FI - PP * UU;
        g_bp[P] = bias[origcol(P)];
    } else if (i < PP * FI + PP * UU + PP + BB * UU) {
        int j = i - PP * FI - PP * UU - PP;
        g_h[0][j] = __float2half_rn(h0[j]);
    }
}

// ================= phase 1: xk = x @ W (fp16 in, fp16 out) =================
// CTA tile 128 rows x 128 cols, K=128. grid (8, 4096): x-tile shared by 8 n-CTAs via L2.
#define G_A 0
#define G_B 34816          // A: 128 rows * 272B
#define G_SMEM (69632 + 32)

__global__ __launch_bounds__(256, 2) void lstm_gemm_x(const float* __restrict__ x) {
    extern __shared__ char sb[];
    const u32 sbase = s2u(sb);
    const int tid = threadIdx.x;
    const int w = tid >> 5, lane = tid & 31;
    const int n0 = blockIdx.x * 128;
    const int b = blockIdx.y >> 3;
    const int t0 = (blockIdx.y & 7) << 7;
    const int mchunk = w & 3;          // 4 x 32 rows
    const int nchunk = w >> 2;         // 2 x 64 cols
    const int q = lane & 3;

    // stage A: x rows -> fp16, stride 272B
    for (int it = 0; it < 16; it++) {
        int idx = tid + it * 256;                 // 4096 float4
        int row = idx >> 5, f4 = idx & 31;
        float4 v = *(const float4*)&x[((size_t)b * TT + t0 + row) * FI + f4 * 4];
        __half2 p0 = __floats2half2_rn(v.x, v.y);
        __half2 p1 = __floats2half2_rn(v.z, v.w);
        *(uint2*)(sb + G_A + row * 272 + f4 * 8) = make_uint2(*(u32*)&p0, *(u32*)&p1);
    }
    // stage B: W^T slice [128 n][128 k], stride 272B
    for (int it = 0; it < 8; it++) {
        int idx = tid + it * 256;                 // 2048 uint4
        int n = idx >> 4, ku = idx & 15;
        *(uint4*)(sb + G_B + n * 272 + ku * 16) =
            *(const uint4*)&g_WT[(n0 + n) * FI + ku * 8];
    }
    __syncthreads();

    const int rA = mchunk * 32 + (lane & 7) + 8 * ((lane >> 3) & 1);
    const int cA = 8 * ((lane >> 4) & 1);
    const u32 aAddr = sbase + G_A + rA * 272 + cA * 2;
    const int rB = nchunk * 64 + (lane & 7) + 8 * ((lane >> 4) & 1);
    const int cB = 8 * ((lane >> 3) & 1);
    const u32 bAddr = sbase + G_B + rB * 272 + cB * 2;

    float C[2][8][4];
#pragma unroll
    for (int m = 0; m < 2; m++)
#pragma unroll
        for (int n = 0; n < 8; n++)
#pragma unroll
            for (int r = 0; r < 4; r++) C[m][n][r] = 0.0f;

#pragma unroll
    for (int k = 0; k < 8; k++) {
        u32 a0[4], a1[4];
        ldsm4(aAddr + k * 32, a0);
        ldsm4(aAddr + 16 * 272 + k * 32, a1);
#pragma unroll
        for (int j = 0; j < 4; j++) {
            u32 bf[4];
            ldsm4(bAddr + j * 16 * 272 + k * 32, bf);
            mma16816(C[0][2 * j],     a0, bf[0], bf[1]);
            mma16816(C[0][2 * j + 1], a0, bf[2], bf[3]);
            mma16816(C[1][2 * j],     a1, bf[0], bf[1]);
            mma16816(C[1][2 * j + 1], a1, bf[2], bf[3]);
        }
    }

    // epilogue: fp16 out
#pragma unroll
    for (int mi = 0; mi < 4; mi++) {
        const int trow = t0 + mchunk * 32 + 8 * mi + (lane >> 2);
        __half* dst = &g_xk[(((size_t)trow * BB) + b) * PP + n0 + nchunk * 64];
        const int m2 = mi >> 1, rr = (mi & 1) * 2;
#pragma unroll
        for (int nn = 0; nn < 8; nn++) {
            __half2 hv = __floats2half2_rn(C[m2][nn][rr], C[m2][nn][rr + 1]);
            *(__half2*)(dst + 8 * nn + 2 * q) = hv;
        }
    }
}

// ================= phase 2: persistent recurrence, 8-CTA clusters =================
// 128 CTAs: mt = blk>>3 (16 groups x 32 batch rows), nt = blk&7 (128 P cols). K=256.
// R^T fragments register-resident; h staged 16KB/step; barrier = hardware cluster barrier.
#define R_SMEM (128 * 528 + 32)

__global__ __launch_bounds__(256, 1) __cluster_dims__(CLU, 1, 1)
void lstm_recur(const float* __restrict__ c0, float* __restrict__ out) {
    extern __shared__ char sb[];
    const u32 sbase = s2u(sb);
    const int tid = threadIdx.x;
    const int w = tid >> 5, lane = tid & 31;
    const int mt = blockIdx.x >> 3;
    const int b_base = mt * 32;
    const int nt = blockIdx.x & 7;
    const int n0 = nt * 128;
    const int q = lane & 3;
    const int row_l = lane >> 2;

    // lane addresses (stride 528B rows in the shared staging region)
    const int rA = (lane & 7) + 8 * ((lane >> 3) & 1);
    const int cA = 8 * ((lane >> 4) & 1);
    const u32 aAddr = sbase + rA * 528 + cA * 2;
    const int rB = w * 16 + (lane & 7) + 8 * ((lane >> 4) & 1);
    const int cB = 8 * ((lane >> 3) & 1);
    const u32 bAddr = sbase + rB * 528 + cB * 2;

    // stage R^T slice [128 n][256 k] -> regs, then region is reused for h staging
    for (int it = 0; it < 16; it++) {
        int idx = tid + it * 256;              // 4096 uint4
        int n = idx >> 5, ku = idx & 31;
        *(uint4*)(sb + n * 528 + ku * 16) = *(const uint4*)&g_RT[(n0 + n) * UU + ku * 8];
    }
    __syncthreads();
    u32 bh[16][4];
#pragma unroll
    for (int k = 0; k < 16; k++) ldsm4(bAddr + k * 32, bh[k]);
    __syncthreads();

    // thread owns all 4 gates of unit u for 4 (row, m2) pairs
    const int B16 = nt * 8 + w;
    const int u = 4 * B16 + q;
    float c_reg[4];
#pragma unroll
    for (int j = 0; j < 4; j++) {
        const int br = b_base + (j >> 1) * 16 + (j & 1) * 8 + row_l;
        c_reg[j] = c0[br * UU + u];
    }
    const float2 b_if = *(const float2*)&g_bp[16 * B16 + 2 * q];
    const float2 b_og = *(const float2*)&g_bp[16 * B16 + 8 + 2 * q];

    for (int t = 0; t < TT; t++) {
        // prefetch xk (fp16) — in flight under staging + mma
        __half2 xk_if[4], xk_og[4];
#pragma unroll
        for (int j = 0; j < 4; j++) {
            const int br = b_base + (j >> 1) * 16 + (j & 1) * 8 + row_l;
            const __half* xp = &g_xk[(((size_t)t * BB) + br) * PP + 16 * B16];
            xk_if[j] = *(const __half2*)(xp + 2 * q);
            xk_og[j] = *(const __half2*)(xp + 8 + 2 * q);
        }

        // stage h: 32 rows x 256 k fp16 = 16KB
        const __half* hsrc = g_h[t & 1];
        for (int it = 0; it < 4; it++) {
            int idx = tid + it * 256;          // 1024 uint4
            int r = idx >> 5, ku = idx & 31;
            *(uint4*)(sb + r * 528 + ku * 16) =
                *(const uint4*)&hsrc[(b_base + r) * UU + ku * 8];
        }
        __syncthreads();

        float C[2][2][4];
#pragma unroll
        for (int m = 0; m < 2; m++)
#pragma unroll
            for (int n = 0; n < 2; n++)
#pragma unroll
                for (int r = 0; r < 4; r++) C[m][n][r] = 0.0f;

#pragma unroll
        for (int k = 0; k < 16; k++) {
            u32 a0[4], a1[4];
            ldsm4(aAddr + k * 32, a0);
            ldsm4(aAddr + 16 * 528 + k * 32, a1);
            mma16816(C[0][0], a0, bh[k][0], bh[k][1]);
            mma16816(C[0][1], a0, bh[k][2], bh[k][3]);
            mma16816(C[1][0], a1, bh[k][0], bh[k][1]);
            mma16816(C[1][1], a1, bh[k][2], bh[k][3]);
        }
        __syncthreads();   // smem reads done before next step's staging overwrites

        // gates
        __half* hdst = g_h[(t + 1) & 1];
#pragma unroll
        for (int j = 0; j < 4; j++) {
            const int m2 = j >> 1, rr = (j & 1) * 2;
            const float zi = C[m2][0][rr]     + __low2float(xk_if[j])  + b_if.x;
            const float zf = C[m2][0][rr + 1] + __high2float(xk_if[j]) + b_if.y;
            const float zo = C[m2][1][rr]     + __low2float(xk_og[j])  + b_og.x;
            const float zg = C[m2][1][rr + 1] + __high2float(xk_og[j]) + b_og.y;
            const float ig = sig_fast(zi);
            const float fg = sig_fast(zf);
            const float og = sig_fast(zo);
            const float gg = tanh_acc(zg);
            const float c = fmaf(fg, c_reg[j], ig * gg);
            c_reg[j] = c;
            const float h = og * tanh_acc(c);
            const int br = b_base + m2 * 16 + (j & 1) * 8 + row_l;
            hdst[br * UU + u] = __float2half_rn(h);
            if (t == TT - 1) out[br * UU + u] = h;
        }

        // hardware cluster barrier: release h writes, acquire peers' h for next step
        asm volatile("barrier.cluster.arrive.aligned;" ::: "memory");
        asm volatile("barrier.cluster.wait.aligned;" ::: "memory");
    }
}

extern "C" void kernel_launch(void* const* d_in, const int* in_sizes, int n_in,
                              void* d_out, int out_size) {
    const float* x    = (const float*)d_in[0];
    const float* W    = (const float*)d_in[1];
    const float* R    = (const float*)d_in[2];
    const float* bias = (const float*)d_in[3];
    const float* h0   = (const float*)d_in[4];
    const float* c0   = (const float*)d_in[5];
    float* out = (float*)d_out;

    cudaFuncSetAttribute(lstm_gemm_x, cudaFuncAttributeMaxDynamicSharedMemorySize, G_SMEM);
    cudaFuncSetAttribute(lstm_recur,  cudaFuncAttributeMaxDynamicSharedMemorySize, R_SMEM);

    const int prep_total = PP * FI + PP * UU + PP + BB * UU;
    lstm_prep<<<(prep_total + 255) / 256, 256>>>(W, R, bias, h0);
    lstm_gemm_x<<<dim3(8, 4096), 256, G_SMEM>>>(x);
    lstm_recur<<<RC_CTAS, 256, R_SMEM>>>(c0, out);
}

// round 13
// speedup vs baseline: 2.0439x; 2.0439x over previous
#include <cuda_runtime.h>
#include <cuda_fp16.h>

typedef unsigned int u32;

#define TT 1024
#define BB 512
#define FI 128
#define UU 256
#define PP 1024        // 4*U permuted: 16-block b16=P>>4; c<8 -> i,f ; c>=8 -> o,g
#define RC_CTAS 256    // 16 batch groups x 16 n-tiles; M=32, N=64, K=256

// ---------------- device scratch ----------------
__device__ __half g_WT[PP * FI];          // W^T permuted [P][f]
__device__ __half g_RT[PP * UU];          // R^T permuted [P][k]
__device__ __half g_h[2][BB * UU];        // h state, double buffered
__device__ float g_bp[PP];
__device__ __half g_xk[(size_t)TT * BB * PP];   // fp16 scratch [(t*512+b)*1024+P]
__device__ unsigned g_cnt[16 * 32];       // per-group barrier (128B padded)
__device__ unsigned g_flag[16 * 32];

// ---------------- helpers ----------------
__device__ __forceinline__ u32 s2u(const void* p) {
    u32 a;
    asm("{ .reg .u64 t; cvta.to.shared.u64 t, %1; cvt.u32.u64 %0, t; }" : "=r"(a) : "l"(p));
    return a;
}
__device__ __forceinline__ void ldsm4(u32 addr, u32* r) {
    asm volatile("ldmatrix.sync.aligned.m8n8.x4.shared.b16 {%0,%1,%2,%3}, [%4];"
                 : "=r"(r[0]), "=r"(r[1]), "=r"(r[2]), "=r"(r[3]) : "r"(addr));
}
__device__ __forceinline__ void mma16816(float* c, const u32* a, u32 b0, u32 b1) {
    asm volatile(
        "mma.sync.aligned.m16n8k16.row.col.f32.f16.f16.f32 "
        "{%0,%1,%2,%3},{%4,%5,%6,%7},{%8,%9},{%0,%1,%2,%3};"
        : "+f"(c[0]), "+f"(c[1]), "+f"(c[2]), "+f"(c[3])
        : "r"(a[0]), "r"(a[1]), "r"(a[2]), "r"(a[3]), "r"(b0), "r"(b1));
}
__device__ __forceinline__ float sig_fast(float x) {
    return __fdividef(1.0f, 1.0f + __expf(-x));
}
__device__ __forceinline__ float tanh_acc(float x) {
    return __fdividef(2.0f, 1.0f + __expf(-2.0f * x)) - 1.0f;
}
__device__ __forceinline__ int origcol(int P) {   // permuted col -> keras col
    int blk = P >> 4, c = P & 15;
    int u = 4 * blk + ((c >> 1) & 3);
    int g = ((c >> 3) << 1) | (c & 1);            // 0:i 1:f 2:o 3:g
    return g * UU + u;
}

// ================= prep =================
__global__ void lstm_prep(const float* __restrict__ W, const float* __restrict__ R,
                          const float* __restrict__ bias, const float* __restrict__ h0) {
    int i = blockIdx.x * blockDim.x + threadIdx.x;
    if (i < PP * FI) {
        int P = i >> 7, f = i & 127;
        g_WT[i] = __float2half_rn(W[f * PP + origcol(P)]);
    } else if (i < PP * FI + PP * UU) {
        int j = i - PP * FI;
        int P = j >> 8, k = j & 255;
        g_RT[j] = __float2half_rn(R[k * PP + origcol(P)]);
    } else if (i < PP * FI + PP * UU + PP) {
        int P = i - PP * FI - PP * UU;
        g_bp[P] = bias[origcol(P)];
    } else if (i < PP * FI + PP * UU + PP + BB * UU) {
        int j = i - PP * FI - PP * UU - PP;
        g_h[0][j] = __float2half_rn(h0[j]);
    }
}

// ================= phase 1: xk = x @ W (fp16 in/out) =================
#define G_A 0
#define G_B 34816          // A: 128 rows * 272B
#define G_SMEM (69632 + 32)

__global__ __launch_bounds__(256, 2) void lstm_gemm_x(const float* __restrict__ x) {
    extern __shared__ char sb[];
    const u32 sbase = s2u(sb);
    const int tid = threadIdx.x;
    const int w = tid >> 5, lane = tid & 31;
    const int n0 = blockIdx.x * 128;
    const int b = blockIdx.y >> 3;
    const int t0 = (blockIdx.y & 7) << 7;
    const int mchunk = w & 3;          // 4 x 32 rows
    const int nchunk = w >> 2;         // 2 x 64 cols
    const int q = lane & 3;

    for (int it = 0; it < 16; it++) {
        int idx = tid + it * 256;                 // 4096 float4
        int row = idx >> 5, f4 = idx & 31;
        float4 v = *(const float4*)&x[((size_t)b * TT + t0 + row) * FI + f4 * 4];
        __half2 p0 = __floats2half2_rn(v.x, v.y);
        __half2 p1 = __floats2half2_rn(v.z, v.w);
        *(uint2*)(sb + G_A + row * 272 + f4 * 8) = make_uint2(*(u32*)&p0, *(u32*)&p1);
    }
    for (int it = 0; it < 8; it++) {
        int idx = tid + it * 256;                 // 2048 uint4
        int n = idx >> 4, ku = idx & 15;
        *(uint4*)(sb + G_B + n * 272 + ku * 16) =
            *(const uint4*)&g_WT[(n0 + n) * FI + ku * 8];
    }
    __syncthreads();

    const int rA = mchunk * 32 + (lane & 7) + 8 * ((lane >> 3) & 1);
    const int cA = 8 * ((lane >> 4) & 1);
    const u32 aAddr = sbase + G_A + rA * 272 + cA * 2;
    const int rB = nchunk * 64 + (lane & 7) + 8 * ((lane >> 4) & 1);
    const int cB = 8 * ((lane >> 3) & 1);
    const u32 bAddr = sbase + G_B + rB * 272 + cB * 2;

    float C[2][8][4];
#pragma unroll
    for (int m = 0; m < 2; m++)
#pragma unroll
        for (int n = 0; n < 8; n++)
#pragma unroll
            for (int r = 0; r < 4; r++) C[m][n][r] = 0.0f;

#pragma unroll
    for (int k = 0; k < 8; k++) {
        u32 a0[4], a1[4];
        ldsm4(aAddr + k * 32, a0);
        ldsm4(aAddr + 16 * 272 + k * 32, a1);
#pragma unroll
        for (int j = 0; j < 4; j++) {
            u32 bf[4];
            ldsm4(bAddr + j * 16 * 272 + k * 32, bf);
            mma16816(C[0][2 * j],     a0, bf[0], bf[1]);
            mma16816(C[0][2 * j + 1], a0, bf[2], bf[3]);
            mma16816(C[1][2 * j],     a1, bf[0], bf[1]);
            mma16816(C[1][2 * j + 1], a1, bf[2], bf[3]);
        }
    }

#pragma unroll
    for (int mi = 0; mi < 4; mi++) {
        const int trow = t0 + mchunk * 32 + 8 * mi + (lane >> 2);
        __half* dst = &g_xk[(((size_t)trow * BB) + b) * PP + n0 + nchunk * 64];
        const int m2 = mi >> 1, rr = (mi & 1) * 2;
#pragma unroll
        for (int nn = 0; nn < 8; nn++) {
            __half2 hv = __floats2half2_rn(C[m2][nn][rr], C[m2][nn][rr + 1]);
            *(__half2*)(dst + 8 * nn + 2 * q) = hv;
        }
    }
}

// ================= phase 2: persistent recurrence, occupancy 2 =================
// 256 CTAs: mt = bx&15 (16 groups x 32 batch rows), nt = bx>>4 (64 P cols). K=256.
// R^T fragments in regs; h staged 16KB/step, double buffered; acq/rel software barrier.
#define R_BUF 16896            // 32 rows * 528B
#define R_SMEM (2 * R_BUF + 32)

__device__ __forceinline__ void group_barrier(int mt, unsigned sense) {
    __syncthreads();
    if (threadIdx.x == 0) {
        unsigned* cnt = &g_cnt[mt * 32];
        unsigned* flag = &g_flag[mt * 32];
        unsigned old;
        asm volatile("atom.add.acq_rel.gpu.global.u32 %0, [%1], 1;"
                     : "=r"(old) : "l"(cnt) : "memory");
        if (old == 15) {
            asm volatile("st.relaxed.gpu.global.u32 [%0], 0;" :: "l"(cnt) : "memory");
            unsigned tmp;
            asm volatile("atom.exch.release.gpu.global.b32 %0, [%1], %2;"
                         : "=r"(tmp) : "l"(flag), "r"(sense) : "memory");
            (void)tmp;
        } else {
            unsigned f;
            do {
                asm volatile("ld.acquire.gpu.global.u32 %0, [%1];"
                             : "=r"(f) : "l"(flag) : "memory");
            } while (f != sense);
        }
    }
    __syncthreads();
}

__global__ __launch_bounds__(256, 2) void lstm_recur(const float* __restrict__ c0,
                                                     float* __restrict__ out) {
    extern __shared__ char sb[];
    const u32 sbase = s2u(sb);
    const int tid = threadIdx.x;
    const int w = tid >> 5, lane = tid & 31;
    const int mt = blockIdx.x & 15;
    const int nt = blockIdx.x >> 4;
    const int b_base = mt * 32;
    const int n0 = nt * 64;
    const int mchunk = w & 1;          // 2 x 16 rows
    const int nchunk = w >> 1;         // 4 x 16 cols
    const int q = lane & 3;
    const int row_l = lane >> 2;

    // stage R^T slice [64 n][256 k] = 2048 uint4 across both buffers (64*528 = 2*R_BUF)
    for (int it = 0; it < 8; it++) {
        int idx = tid + it * 256;              // 2048 uint4
        int n = idx >> 5, ku = idx & 31;
        *(uint4*)(sb + n * 528 + ku * 16) = *(const uint4*)&g_RT[(n0 + n) * UU + ku * 8];
    }
    __syncthreads();
    const int rB = nchunk * 16 + (lane & 7) + 8 * ((lane >> 4) & 1);
    const int cB = 8 * ((lane >> 3) & 1);
    const u32 bAddr = sbase + rB * 528 + cB * 2;
    u32 bh[16][4];
#pragma unroll
    for (int k = 0; k < 16; k++) ldsm4(bAddr + k * 32, bh[k]);
    __syncthreads();

    // A lane offset (within a buffer)
    const int rA = mchunk * 16 + (lane & 7) + 8 * ((lane >> 3) & 1);
    const int cA = 8 * ((lane >> 4) & 1);
    const u32 aOff = rA * 528 + cA * 2;

    // thread owns all 4 gates of unit u for 2 batch rows (br0, br0+8)
    const int B16 = nt * 4 + nchunk;
    const int u = 4 * B16 + q;
    const int br0 = b_base + mchunk * 16 + row_l;
    float c_reg[2] = { c0[br0 * UU + u], c0[(br0 + 8) * UU + u] };
    const float2 b_if = *(const float2*)&g_bp[16 * B16 + 2 * q];
    const float2 b_og = *(const float2*)&g_bp[16 * B16 + 8 + 2 * q];

    unsigned sense = 0;

    for (int t = 0; t < TT; t++) {
        // prefetch xk (fp16) — consumed after the mma loop
        const __half* xp0 = &g_xk[(((size_t)t * BB) + br0) * PP + 16 * B16];
        const __half2 xi0 = *(const __half2*)(xp0 + 2 * q);
        const __half2 xo0 = *(const __half2*)(xp0 + 8 + 2 * q);
        const __half2 xi1 = *(const __half2*)(xp0 + 8 * PP + 2 * q);
        const __half2 xo1 = *(const __half2*)(xp0 + 8 * PP + 8 + 2 * q);

        // stage h: 32 rows x 256 k fp16 = 16KB = 1024 uint4 into buffer t&1
        const __half* hsrc = g_h[t & 1];
        const u32 bufo = (u32)(t & 1) * R_BUF;
        for (int it = 0; it < 4; it++) {
            int idx = tid + it * 256;          // 1024 uint4
            int r = idx >> 5, ku = idx & 31;
            *(uint4*)(sb + bufo + r * 528 + ku * 16) =
                *(const uint4*)&hsrc[(b_base + r) * UU + ku * 8];
        }
        __syncthreads();

        float C[2][4];
#pragma unroll
        for (int n = 0; n < 2; n++)
#pragma unroll
            for (int r = 0; r < 4; r++) C[n][r] = 0.0f;

        const u32 aAddr = sbase + bufo + aOff;
#pragma unroll
        for (int k = 0; k < 16; k++) {
            u32 a0[4];
            ldsm4(aAddr + k * 32, a0);
            mma16816(C[0], a0, bh[k][0], bh[k][1]);
            mma16816(C[1], a0, bh[k][2], bh[k][3]);
        }

        // gates: rows br0 (C[.][0..1]) and br0+8 (C[.][2..3])
        __half* hdst = g_h[(t + 1) & 1];
#pragma unroll
        for (int j = 0; j < 2; j++) {
            const int rr = 2 * j;
            const __half2 xi = j ? xi1 : xi0;
            const __half2 xo = j ? xo1 : xo0;
            const float zi = C[0][rr]     + __low2float(xi)  + b_if.x;
            const float zf = C[0][rr + 1] + __high2float(xi) + b_if.y;
            const float zo = C[1][rr]     + __low2float(xo)  + b_og.x;
            const float zg = C[1][rr + 1] + __high2float(xo) + b_og.y;
            const float ig = sig_fast(zi);
            const float fg = sig_fast(zf);
            const float og = sig_fast(zo);
            const float gg = tanh_acc(zg);
            const float c = fmaf(fg, c_reg[j], ig * gg);
            c_reg[j] = c;
            const float h = og * tanh_acc(c);
            const int br = br0 + 8 * j;
            hdst[br * UU + u] = __float2half_rn(h);
            if (t == TT - 1) out[br * UU + u] = h;
        }

        group_barrier(mt, sense ^= 1);   // 1024 flips -> flag returns to 0 for replay
    }
}

extern "C" void kernel_launch(void* const* d_in, const int* in_sizes, int n_in,
                              void* d_out, int out_size) {
    const float* x    = (const float*)d_in[0];
    const float* W    = (const float*)d_in[1];
    const float* R    = (const float*)d_in[2];
    const float* bias = (const float*)d_in[3];
    const float* h0   = (const float*)d_in[4];
    const float* c0   = (const float*)d_in[5];
    float* out = (float*)d_out;

    cudaFuncSetAttribute(lstm_gemm_x, cudaFuncAttributeMaxDynamicSharedMemorySize, G_SMEM);
    cudaFuncSetAttribute(lstm_recur,  cudaFuncAttributeMaxDynamicSharedMemorySize, R_SMEM);

    const int prep_total = PP * FI + PP * UU + PP + BB * UU;
    lstm_prep<<<(prep_total + 255) / 256, 256>>>(W, R, bias, h0);
    lstm_gemm_x<<<dim3(8, 4096), 256, G_SMEM>>>(x);
    lstm_recur<<<RC_CTAS, 256, R_SMEM>>>(c0, out);
}

// round 15
// speedup vs baseline: 2.1158x; 1.0352x over previous
#include <cuda_runtime.h>
#include <cuda_fp16.h>

typedef unsigned int u32;

#define TT 1024
#define BB 512
#define FI 128
#define UU 256
#define PP 1024        // 4*U permuted: 16-block b16=P>>4; c<8 -> i,f ; c>=8 -> o,g
#define RC_CTAS 256    // 16 batch groups x 16 n-tiles; M=32, N=64, K=256(h)+128(x)

// ---------------- device scratch ----------------
__device__ __half g_WT[PP * FI];          // W^T permuted [P][f]
__device__ __half g_RT[PP * UU];          // R^T permuted [P][k]
__device__ __half g_h[2][BB * UU];        // h state, double buffered
__device__ float g_bp[PP];
__device__ __half g_x16[(size_t)TT * BB * FI];  // x transposed+fp16: [t][b][f]
__device__ unsigned g_cnt[16 * 32];       // per-group barrier (128B padded)
__device__ unsigned g_flag[16 * 32];

// ---------------- helpers ----------------
__device__ __forceinline__ u32 s2u(const void* p) {
    u32 a;
    asm("{ .reg .u64 t; cvta.to.shared.u64 t, %1; cvt.u32.u64 %0, t; }" : "=r"(a) : "l"(p));
    return a;
}
__device__ __forceinline__ void ldsm4(u32 addr, u32* r) {
    asm volatile("ldmatrix.sync.aligned.m8n8.x4.shared.b16 {%0,%1,%2,%3}, [%4];"
                 : "=r"(r[0]), "=r"(r[1]), "=r"(r[2]), "=r"(r[3]) : "r"(addr));
}
__device__ __forceinline__ void mma16816(float* c, const u32* a, u32 b0, u32 b1) {
    asm volatile(
        "mma.sync.aligned.m16n8k16.row.col.f32.f16.f16.f32 "
        "{%0,%1,%2,%3},{%4,%5,%6,%7},{%8,%9},{%0,%1,%2,%3};"
        : "+f"(c[0]), "+f"(c[1]), "+f"(c[2]), "+f"(c[3])
        : "r"(a[0]), "r"(a[1]), "r"(a[2]), "r"(a[3]), "r"(b0), "r"(b1));
}
__device__ __forceinline__ float sig_fast(float x) {
    return __fdividef(1.0f, 1.0f + __expf(-x));
}
__device__ __forceinline__ float tanh_acc(float x) {
    return __fdividef(2.0f, 1.0f + __expf(-2.0f * x)) - 1.0f;
}
__device__ __forceinline__ int origcol(int P) {   // permuted col -> keras col
    int blk = P >> 4, c = P & 15;
    int u = 4 * blk + ((c >> 1) & 3);
    int g = ((c >> 3) << 1) | (c & 1);            // 0:i 1:f 2:o 3:g
    return g * UU + u;
}

// ================= prep: weights / bias / h0 =================
__global__ void lstm_prep(const float* __restrict__ W, const float* __restrict__ R,
                          const float* __restrict__ bias, const float* __restrict__ h0) {
    int i = blockIdx.x * blockDim.x + threadIdx.x;
    if (i < PP * FI) {
        int P = i >> 7, f = i & 127;
        g_WT[i] = __float2half_rn(W[f * PP + origcol(P)]);
    } else if (i < PP * FI + PP * UU) {
        int j = i - PP * FI;
        int P = j >> 8, k = j & 255;
        g_RT[j] = __float2half_rn(R[k * PP + origcol(P)]);
    } else if (i < PP * FI + PP * UU + PP) {
        int P = i - PP * FI - PP * UU;
        g_bp[P] = bias[origcol(P)];
    } else if (i < PP * FI + PP * UU + PP + BB * UU) {
        int j = i - PP * FI - PP * UU - PP;
        g_h[0][j] = __float2half_rn(h0[j]);
    }
}

// ================= prep: x -> fp16 [t][b][f] =================
__global__ void lstm_prep_x(const float* __restrict__ x) {
    const int bx = blockIdx.x;           // t*BB + b
    const int t = bx >> 9;               // /BB
    const int b = bx & (BB - 1);
    const int f = threadIdx.x;           // 128 threads
    g_x16[(size_t)bx * FI + f] = __float2half_rn(x[((size_t)b * TT + t) * FI + f]);
}

// ================= persistent recurrence (fused x@W + h@R) =================
// 256 CTAs: mt = bx&15 (16 groups x 32 batch rows), nt = bx>>4 (64 P cols).
// Per step: C = h@R (K=256, B-frags in regs) + x_t@W (K=128, B-frags ldsm from smem).
#define S_H0 0                 // h buffer 0: 32 rows * 528B = 16896
#define S_H1 16896             // h buffer 1
#define S_W  33792             // W^T slice: 64 n * 272B = 17408
#define S_X0 51200             // x buffer 0: 32 rows * 272B = 8704
#define S_X1 59904             // x buffer 1
#define R_SMEM (68608 + 32)

__global__ __launch_bounds__(256, 2) void lstm_recur(const float* __restrict__ c0,
                                                     float* __restrict__ out) {
    extern __shared__ char sb[];
    const u32 sbase = s2u(sb);
    const int tid = threadIdx.x;
    const int w = tid >> 5, lane = tid & 31;
    const int mt = blockIdx.x & 15;
    const int nt = blockIdx.x >> 4;
    const int b_base = mt * 32;
    const int n0 = nt * 64;
    const int mchunk = w & 1;          // 2 x 16 rows
    const int nchunk = w >> 1;         // 4 x 16 cols
    const int q = lane & 3;
    const int row_l = lane >> 2;

    // --- init: stage R^T [64 n][256 k] across h-buffers (2048 uint4), frags -> regs
    for (int it = 0; it < 8; it++) {
        int idx = tid + it * 256;
        int n = idx >> 5, ku = idx & 31;
        *(uint4*)(sb + n * 528 + ku * 16) = *(const uint4*)&g_RT[(n0 + n) * UU + ku * 8];
    }
    __syncthreads();
    const int rB = nchunk * 16 + (lane & 7) + 8 * ((lane >> 4) & 1);
    const int cB = 8 * ((lane >> 3) & 1);
    u32 bh[16][4];
    {
        const u32 bAddr = sbase + rB * 528 + cB * 2;
#pragma unroll
        for (int k = 0; k < 16; k++) ldsm4(bAddr + k * 32, bh[k]);
    }
    __syncthreads();

    // --- init: stage W^T slice [64 n][128 k] (1024 uint4) into S_W (persistent)
    for (int it = 0; it < 4; it++) {
        int idx = tid + it * 256;
        int n = idx >> 4, ku = idx & 15;
        *(uint4*)(sb + S_W + n * 272 + ku * 16) = *(const uint4*)&g_WT[(n0 + n) * FI + ku * 8];
    }
    // --- init: stage x(0) into xbuf 0 (512 uint4)
    for (int it = 0; it < 2; it++) {
        int idx = tid + it * 256;
        int r = idx >> 4, ku = idx & 15;
        *(uint4*)(sb + S_X0 + r * 272 + ku * 16) =
            *(const uint4*)&g_x16[((size_t)0 * BB + b_base + r) * FI + ku * 8];
    }
    const u32 bAddrW = sbase + S_W + rB * 272 + cB * 2;

    // A lane offsets
    const int rA = mchunk * 16 + (lane & 7) + 8 * ((lane >> 3) & 1);
    const int cA = 8 * ((lane >> 4) & 1);
    const u32 aOffH = rA * 528 + cA * 2;   // within h buffer
    const u32 aOffX = rA * 272 + cA * 2;   // within x buffer

    // thread owns all 4 gates of unit u for rows br0, br0+8
    const int B16 = nt * 4 + nchunk;
    const int u = 4 * B16 + q;
    const int br0 = b_base + mchunk * 16 + row_l;
    float c_reg[2] = { c0[br0 * UU + u], c0[(br0 + 8) * UU + u] };
    const float2 b_if = *(const float2*)&g_bp[16 * B16 + 2 * q];
    const float2 b_og = *(const float2*)&g_bp[16 * B16 + 8 + 2 * q];

    unsigned* const cnt = &g_cnt[mt * 32];
    unsigned* const flag = &g_flag[mt * 32];
    unsigned sense = 0;

    for (int t = 0; t < TT; t++) {
        // stage h(t): 1024 uint4 into h buffer t&1
        const __half* hsrc = g_h[t & 1];
        const u32 hbuf = (u32)(t & 1) * 16896u;
        for (int it = 0; it < 4; it++) {
            int idx = tid + it * 256;
            int r = idx >> 5, ku = idx & 31;
            *(uint4*)(sb + hbuf + r * 528 + ku * 16) =
                *(const uint4*)&hsrc[(b_base + r) * UU + ku * 8];
        }
        __syncthreads();

        float C[2][4];
#pragma unroll
        for (int n = 0; n < 2; n++)
#pragma unroll
            for (int r = 0; r < 4; r++) C[n][r] = 0.0f;

        // h @ R : 16 k-steps, B in regs
        const u32 aAddrH = sbase + hbuf + aOffH;
#pragma unroll
        for (int k = 0; k < 16; k++) {
            u32 a0[4];
            ldsm4(aAddrH + k * 32, a0);
            mma16816(C[0], a0, bh[k][0], bh[k][1]);
            mma16816(C[1], a0, bh[k][2], bh[k][3]);
        }
        // x_t @ W : 8 k-steps, B ldsm'd from persistent W slice
        const u32 aAddrX = sbase + ((t & 1) ? S_X1 : S_X0) + aOffX;
#pragma unroll
        for (int k = 0; k < 8; k++) {
            u32 a0[4], bw[4];
            ldsm4(aAddrX + k * 32, a0);
            ldsm4(bAddrW + k * 32, bw);
            mma16816(C[0], a0, bw[0], bw[1]);
            mma16816(C[1], a0, bw[2], bw[3]);
        }

        // gates: rows br0 (C[.][0..1]) and br0+8 (C[.][2..3])
        __half* hdst = g_h[(t + 1) & 1];
#pragma unroll
        for (int j = 0; j < 2; j++) {
            const int rr = 2 * j;
            const float zi = C[0][rr]     + b_if.x;
            const float zf = C[0][rr + 1] + b_if.y;
            const float zo = C[1][rr]     + b_og.x;
            const float zg = C[1][rr + 1] + b_og.y;
            const float ig = sig_fast(zi);
            const float fg = sig_fast(zf);
            const float og = sig_fast(zo);
            const float gg = tanh_acc(zg);
            const float c = fmaf(fg, c_reg[j], ig * gg);
            c_reg[j] = c;
            const float h = og * tanh_acc(c);
            const int br = br0 + 8 * j;
            hdst[br * UU + u] = __float2half_rn(h);
            if (t == TT - 1) out[br * UU + u] = h;
        }
        __syncthreads();

        // split barrier: arrive, stage x(t+1) under the wait, then wait
        sense ^= 1;
        if (tid == 0) {
            unsigned old;
            asm volatile("atom.add.acq_rel.gpu.global.u32 %0, [%1], 1;"
                         : "=r"(old) : "l"(cnt) : "memory");
            if (old == 15) {
                asm volatile("st.relaxed.gpu.global.u32 [%0], 0;" :: "l"(cnt) : "memory");
                unsigned tmp;
                asm volatile("atom.exch.release.gpu.global.b32 %0, [%1], %2;"
                             : "=r"(tmp) : "l"(flag), "r"(sense) : "memory");
                (void)tmp;
            }
        }
        if (t + 1 < TT) {   // x staging is barrier-independent
            const u32 xbuf = ((t + 1) & 1) ? S_X1 : S_X0;
            for (int it = 0; it < 2; it++) {
                int idx = tid + it * 256;
                int r = idx >> 4, ku = idx & 15;
                *(uint4*)(sb + xbuf + r * 272 + ku * 16) =
                    *(const uint4*)&g_x16[((size_t)(t + 1) * BB + b_base + r) * FI + ku * 8];
            }
        }
        if (tid == 0) {
            unsigned f;
            do {
                asm volatile("ld.acquire.gpu.global.u32 %0, [%1];"
                             : "=r"(f) : "l"(flag) : "memory");
            } while (f != sense);
        }
        __syncthreads();
    }
}

extern "C" void kernel_launch(void* const* d_in, const int* in_sizes, int n_in,
                              void* d_out, int out_size) {
    const float* x    = (const float*)d_in[0];
    const float* W    = (const float*)d_in[1];
    const float* R    = (const float*)d_in[2];
    const float* bias = (const float*)d_in[3];
    const float* h0   = (const float*)d_in[4];
    const float* c0   = (const float*)d_in[5];
    float* out = (float*)d_out;

    cudaFuncSetAttribute(lstm_recur, cudaFuncAttributeMaxDynamicSharedMemorySize, R_SMEM);

    const int prep_total = PP * FI + PP * UU + PP + BB * UU;
    lstm_prep<<<(prep_total + 255) / 256, 256>>>(W, R, bias, h0);
    lstm_prep_x<<<TT * BB, FI>>>(x);
    lstm_recur<<<RC_CTAS, 256, R_SMEM>>>(c0, out);
}